// round 13
// baseline (speedup 1.0000x reference)
#include <cuda_runtime.h>
#include <cuda_bf16.h>
#include <cstdint>

// Problem dims
#define L_SEQ   4096
#define HID     2048
#define EMB     1024
#define G4      8192      // 4*HID
#define NLET    256

// Scan kernel config
#define NB      128       // persistent worker blocks; +1 aggregator block
#define TPB     1024
#define HPB     16        // h indices per block

// Dual-row packed weights: u32 = {bf16 W[2k][c] (lo), bf16 W[2k+1][c] (hi)}
#define SDR     24
#define W_S_BYTES   (SDR * HID * 4)              // 196608 (24 dual-rows x 2048 u32)
#define SCAN_SMEM   (W_S_BYTES + 2 * 64 * 4 * 4) // + red[2][64][4] f32

// ---------------- device globals (scratch; no allocation allowed) ----------------
__device__ unsigned g_Whd[(size_t)(G4 / 2) * HID];     // 32 MB dual-row packed bf16 weights
__device__ float g_xg[(size_t)NLET * G4];              // 8 MB gate table
__device__ float g_hs[(size_t)(L_SEQ + 1) * HID];      // 32 MB h history (row 0 = h0)
__device__ float g_cL[HID];
__device__ __align__(128) unsigned g_flagsc[NB];       // compact per-block flags (1 writer; aggregator-only pollers)
// 16 sub-epochs (one per 128-col chunk = 8 producer blocks), 8 replicas each,
// 256B stride, single writer per word.
__device__ unsigned g_epoch[16 * 8 * 64];

// ---------------- helpers ----------------
__device__ __forceinline__ unsigned ld_acq(const unsigned* p) {
    unsigned v;
    asm volatile("ld.global.acquire.gpu.u32 %0, [%1];" : "=r"(v) : "l"(p) : "memory");
    return v;
}
__device__ __forceinline__ void st_rel(unsigned* p, unsigned v) {
    asm volatile("st.global.release.gpu.u32 [%0], %1;" :: "l"(p), "r"(v) : "memory");
}

__device__ __forceinline__ float sigmoid_f(float x) {
    return __fdividef(1.f, 1.f + __expf(-x));
}
__device__ __forceinline__ float tanh_f(float x) {
    float xc = fminf(fmaxf(x, -15.f), 15.f);
    float e2 = __expf(2.f * xc);
    return __fdividef(e2 - 1.f, e2 + 1.f);
}

// {h,h} packed f32x2
__device__ __forceinline__ unsigned long long splat2(float h) {
    unsigned long long r;
    asm("mov.b64 %0, {%1, %1};" : "=l"(r) : "f"(h));
    return r;
}
// acc(f32x2) += {bf16lo(u), bf16hi(u)} * hs   (2 fp32 MACs, exact fp32 math)
__device__ __forceinline__ void ffma2c(unsigned long long& acc, unsigned u, unsigned long long hs) {
    asm("{\n\t"
        ".reg .b32 lo, hi;\n\t"
        ".reg .b64 wp;\n\t"
        "shl.b32 lo, %1, 16;\n\t"
        "and.b32 hi, %1, 0xffff0000;\n\t"
        "mov.b64 wp, {lo, hi};\n\t"
        "fma.rn.f32x2 %0, wp, %2, %0;\n\t"
        "}" : "+l"(acc) : "r"(u), "l"(hs));
}
__device__ __forceinline__ void unpack2(unsigned long long a, float& x, float& y) {
    asm("mov.b64 {%0, %1}, %2;" : "=f"(x), "=f"(y) : "l"(a));
}

// One 128-col chunk of the dual-row dot: 16 u32 weights x 4 splatted h values.
__device__ __forceinline__ void chunk_fma(float4 h, uint4 w0, uint4 w1, uint4 w2, uint4 w3,
                                          unsigned long long& ac0, unsigned long long& ac1,
                                          unsigned long long& ac2, unsigned long long& ac3) {
    unsigned long long hs0 = splat2(h.x);
    unsigned long long hs1 = splat2(h.y);
    unsigned long long hs2 = splat2(h.z);
    unsigned long long hs3 = splat2(h.w);
    ffma2c(ac0, w0.x, hs0); ffma2c(ac0, w0.y, hs1); ffma2c(ac0, w0.z, hs2); ffma2c(ac0, w0.w, hs3);
    ffma2c(ac1, w1.x, hs0); ffma2c(ac1, w1.y, hs1); ffma2c(ac1, w1.z, hs2); ffma2c(ac1, w1.w, hs3);
    ffma2c(ac2, w2.x, hs0); ffma2c(ac2, w2.y, hs1); ffma2c(ac2, w2.z, hs2); ffma2c(ac2, w2.w, hs3);
    ffma2c(ac3, w3.x, hs0); ffma2c(ac3, w3.y, hs1); ffma2c(ac3, w3.z, hs2); ffma2c(ac3, w3.w, hs3);
}

// ---------------- K0: reset barrier state, init hs[0] = h0 ----------------
__global__ void init_kernel(const float* __restrict__ h0) {
    int i = blockIdx.x * blockDim.x + threadIdx.x;
    if (i < HID) g_hs[i] = h0[i];
    if (i < NB) g_flagsc[i] = 0u;
    if (i < 16 * 8 * 64) g_epoch[i] = 0u;
}

// ---------------- K1: convert W_hh fp32 -> dual-row packed bf16 ----------------
__global__ void conv_kernel(const float* __restrict__ W) {
    size_t n = (size_t)(G4 / 2) * HID;
    size_t stride = (size_t)gridDim.x * blockDim.x;
    for (size_t idx = blockIdx.x * (size_t)blockDim.x + threadIdx.x; idx < n; idx += stride) {
        size_t dr = idx >> 11, c = idx & 2047;
        float w0 = W[(2 * dr) * HID + c];
        float w1 = W[(2 * dr + 1) * HID + c];
        __nv_bfloat162 p = __floats2bfloat162_rn(w0, w1);   // .x = lo = even row
        g_Whd[idx] = *reinterpret_cast<unsigned*>(&p);
    }
}

// ---------------- K2: xg_table[256,8192] = W_emb @ W_ih^T + (b_ih+b_hh) ----------------
__global__ void xg_gemm(const float* __restrict__ A /*W_emb [256,1024]*/,
                        const float* __restrict__ B /*W_ih [8192,1024]*/,
                        const float* __restrict__ b_ih,
                        const float* __restrict__ b_hh) {
    __shared__ float As[16][65];
    __shared__ float Bs[16][65];
    int jt = blockIdx.x * 64;   // gate dim
    int lt = blockIdx.y * 64;   // letter dim
    int tid = threadIdx.x;
    int tx = tid & 15, ty = tid >> 4;
    float acc[4][4] = {};
    for (int k0 = 0; k0 < EMB; k0 += 16) {
        #pragma unroll
        for (int i = 0; i < 4; i++) {
            int idx = tid + i * 256;
            int k = idx & 15, l = idx >> 4;
            As[k][l] = A[(size_t)(lt + l) * EMB + k0 + k];
            Bs[k][l] = B[(size_t)(jt + l) * EMB + k0 + k];
        }
        __syncthreads();
        #pragma unroll
        for (int k = 0; k < 16; k++) {
            float a[4], bb[4];
            #pragma unroll
            for (int i = 0; i < 4; i++) a[i] = As[k][ty * 4 + i];
            #pragma unroll
            for (int j = 0; j < 4; j++) bb[j] = Bs[k][tx * 4 + j];
            #pragma unroll
            for (int i = 0; i < 4; i++)
                #pragma unroll
                for (int j = 0; j < 4; j++)
                    acc[i][j] = fmaf(a[i], bb[j], acc[i][j]);
        }
        __syncthreads();
    }
    #pragma unroll
    for (int i = 0; i < 4; i++) {
        int l = lt + ty * 4 + i;
        #pragma unroll
        for (int j = 0; j < 4; j++) {
            int jj = jt + tx * 4 + j;
            g_xg[(size_t)l * G4 + jj] = acc[i][j] + b_ih[jj] + b_hh[jj];
        }
    }
}

// ---------------- K3: persistent LSTM scan ----------------
// Worker block b (0..127): as R12 (dual-row packed weights, 24 dual-rows smem,
// 1 dual-row in regs). Warp (rg,cg) processes 4 chunks of 128 cols; chunk q
// depends only on sub-epoch cg*4+q (8 producer blocks). Waits are pipelined:
// next chunk's epoch word is prefetched before computing the current chunk.
// Block 128 = aggregator: warp s (0..15) polls its 8 flags (one line) and
// releases epoch[s] (8 single-writer replicas) as soon as they land.
__global__ void __launch_bounds__(TPB, 1)
scan_kernel(const int* __restrict__ ids, const float* __restrict__ c0) {
    const int tid = threadIdx.x;
    const int b   = blockIdx.x;

    // ---- aggregator block ----
    if (b == NB) {
        const int w = tid >> 5, lane = tid & 31;
        if (w < 16) {  // warp w owns sub-group w (blocks 8w .. 8w+7)
            const unsigned* f = &g_flagsc[w * 8 + (lane & 7)];
            unsigned* myep = &g_epoch[w * 512 + lane * 64];
            for (int e = 1; e < L_SEQ; e++) {
                const unsigned tgt = (unsigned)e;
                for (;;) {
                    bool ok = (ld_acq(f) >= tgt);
                    if (__all_sync(0xffffffffu, ok)) break;
                }
                if (lane < 8) st_rel(myep, tgt);
            }
        }
        return;
    }

    extern __shared__ char smraw[];
    uint4* w_s4 = (uint4*)smraw;                          // 24 dual-rows * 512 uint4
    float* red = (float*)(smraw + W_S_BYTES);             // [2][64][4] partials
    float4* red4 = (float4*)red;

    const int base = b * HPB;

    // Preload the 24 smem-resident dual-rows.
    const uint4* whd4 = (const uint4*)g_Whd;              // 512 uint4 per dual-row
    for (int i = tid; i < SDR * 512; i += TPB) {
        int s = i >> 9, r = i & 511;
        int prg = s / 3, p = s - prg * 3;
        int dr = (prg >> 1) * 1024 + 8 * b + ((prg & 1) << 2) + p;
        w_s4[i] = whd4[(size_t)dr * 512 + r];
    }
    float c_reg = 0.f;
    if (tid < HPB) c_reg = c0[base + tid];
    __syncthreads();

    const int w = tid >> 5, lane = tid & 31;
    const int rg = w >> 2;           // row group 0..7
    const int cg = w & 3;            // column group 0..3
    const int gate = rg >> 1;
    const uint4* ws = w_s4 + (size_t)(rg * 3) * 512 + (cg * 128 + lane);
    // sub-epoch base for chunk q = cg*4+q: ep0 + q*512
    const unsigned* ep0 = &g_epoch[(cg * 4) * 512 + ((b + rg) & 7) * 64];
    unsigned* own_flag_w = &g_flagsc[b];

    // Loop-invariant streamed dual-row (rows 6,7 of this row-group): load ONCE.
    uint4 sw[4];
    {
        int dr = gate * 1024 + 8 * b + ((rg & 1) << 2) + 3;
        const uint4* wp_g = whd4 + (size_t)dr * 512 + (cg * 128 + lane);
        #pragma unroll
        for (int q = 0; q < 4; q++) sw[q] = wp_g[q * 32];
    }

    for (int t = 0; t < L_SEQ; t++) {
        // Prefetch xg row + letter id (independent of h — start immediately)
        float xg0, xg1, xg2, xg3;
        if (tid < HPB) {
            int sid = __ldg(&ids[t]);
            const float* xr = g_xg + (size_t)sid * G4 + base + tid;
            xg0 = __ldg(xr);
            xg1 = __ldg(xr + HID);
            xg2 = __ldg(xr + 2 * HID);
            xg3 = __ldg(xr + 3 * HID);
        }

        const unsigned tgt = (unsigned)t;
        const float4* hb = (const float4*)(g_hs + (size_t)t * HID) + cg * 128;
        unsigned long long ac0 = 0ull, ac1 = 0ull, ac2 = 0ull, ac3 = 0ull;
        unsigned pv;
        float4 h;

        // ---- chunk 0: wait, then compute while prefetching chunk 1's epoch ----
        if (t > 0) { while (ld_acq(ep0) < tgt) {} }
        h = hb[lane];
        pv = (t > 0) ? ld_acq(ep0 + 512) : 0u;
        chunk_fma(h, ws[0], ws[512], ws[1024], sw[0], ac0, ac1, ac2, ac3);

        // ---- chunk 1 ----
        if (t > 0 && pv < tgt) { while (ld_acq(ep0 + 512) < tgt) {} }
        h = hb[32 + lane];
        pv = (t > 0) ? ld_acq(ep0 + 1024) : 0u;
        chunk_fma(h, ws[32], ws[544], ws[1056], sw[1], ac0, ac1, ac2, ac3);

        // ---- chunk 2 ----
        if (t > 0 && pv < tgt) { while (ld_acq(ep0 + 1024) < tgt) {} }
        h = hb[64 + lane];
        pv = (t > 0) ? ld_acq(ep0 + 1536) : 0u;
        chunk_fma(h, ws[64], ws[576], ws[1088], sw[2], ac0, ac1, ac2, ac3);

        // ---- chunk 3 ----
        if (t > 0 && pv < tgt) { while (ld_acq(ep0 + 1536) < tgt) {} }
        h = hb[96 + lane];
        chunk_fma(h, ws[96], ws[608], ws[1120], sw[3], ac0, ac1, ac2, ac3);

        float acc[8];
        unpack2(ac0, acc[0], acc[1]);
        unpack2(ac1, acc[2], acc[3]);
        unpack2(ac2, acc[4], acc[5]);
        unpack2(ac3, acc[6], acc[7]);

        // Select-exchange multi-row reduction: 8 row-sums in ~35 instrs.
        float a4[4];
        #pragma unroll
        for (int r = 0; r < 4; r++) {
            float send = (lane & 16) ? acc[r] : acc[r + 4];
            float recv = __shfl_xor_sync(0xffffffffu, send, 16);
            float keep = (lane & 16) ? acc[r + 4] : acc[r];
            a4[r] = keep + recv;
        }
        float a2[2];
        #pragma unroll
        for (int r = 0; r < 2; r++) {
            float send = (lane & 8) ? a4[r] : a4[r + 2];
            float recv = __shfl_xor_sync(0xffffffffu, send, 8);
            float keep = (lane & 8) ? a4[r + 2] : a4[r];
            a2[r] = keep + recv;
        }
        {
            float send = (lane & 4) ? a2[0] : a2[1];
            float recv = __shfl_xor_sync(0xffffffffu, send, 4);
            float keep = (lane & 4) ? a2[1] : a2[0];
            float a1 = keep + recv;
            a1 += __shfl_xor_sync(0xffffffffu, a1, 2);
            a1 += __shfl_xor_sync(0xffffffffu, a1, 1);
            if ((lane & 3) == 0) {
                int row = ((lane >> 2) & 1) | (((lane >> 3) & 1) << 1) | (((lane >> 4) & 1) << 2);
                red[(t & 1) * 256 + (rg * 8 + row) * 4 + cg] = a1;
            }
        }
        __syncthreads();

        // fused combine + LSTM cell update (PyTorch gate order i,f,g,o)
        if (tid < HPB) {
            const float4* rp = red4 + (t & 1) * 64;
            float4 r0 = rp[tid];            // gate i partials
            float4 r1 = rp[16 + tid];       // gate f
            float4 r2 = rp[32 + tid];       // gate g
            float4 r3 = rp[48 + tid];       // gate o
            float gi = r0.x + r0.y + r0.z + r0.w + xg0;
            float gf = r1.x + r1.y + r1.z + r1.w + xg1;
            float gg = r2.x + r2.y + r2.z + r2.w + xg2;
            float go = r3.x + r3.y + r3.z + r3.w + xg3;
            float i_ = sigmoid_f(gi);
            float f_ = sigmoid_f(gf);
            float g_ = tanh_f(gg);
            float o_ = sigmoid_f(go);
            c_reg = f_ * c_reg + i_ * g_;
            float hn = o_ * tanh_f(c_reg);
            g_hs[(size_t)(t + 1) * HID + base + tid] = hn;
            if (t == L_SEQ - 1) g_cL[base + tid] = c_reg;
        }
        __syncwarp();
        if (tid == 0) st_rel(own_flag_w, (unsigned)(t + 1));
    }
}

// ---------------- K4: logits + relu + log_softmax ----------------
__global__ void out_kernel(const float* __restrict__ W_out,
                           const float* __restrict__ b_out,
                           float* __restrict__ out) {
    extern __shared__ float sh[];                    // 16*2048 floats
    int t0 = blockIdx.x * 16;
    int tid = threadIdx.x;

    const float4* src = (const float4*)(g_hs + (size_t)(t0 + 1) * HID);
    float4* dst = (float4*)sh;
    #pragma unroll
    for (int i = 0; i < 32; i++) dst[tid + i * 256] = src[tid + i * 256];
    __syncthreads();

    float acc[16];
    #pragma unroll
    for (int tt = 0; tt < 16; tt++) acc[tt] = 0.f;
    const float4* wrow = (const float4*)(W_out + (size_t)tid * HID);
    for (int e4 = 0; e4 < HID / 4; e4++) {
        float4 wv = wrow[e4];
        #pragma unroll
        for (int tt = 0; tt < 16; tt++) {
            float4 h = ((const float4*)(sh + tt * HID))[e4];
            acc[tt] = fmaf(wv.x, h.x, fmaf(wv.y, h.y, fmaf(wv.z, h.z, fmaf(wv.w, h.w, acc[tt]))));
        }
    }
    float bn = b_out[tid];
    __syncthreads();                                  // reuse sh as logits tile [16][256]
    #pragma unroll
    for (int tt = 0; tt < 16; tt++)
        sh[tt * 256 + tid] = fmaxf(acc[tt] + bn, 0.f);   // relu BEFORE softmax (matches ref)
    __syncthreads();

    int w = tid >> 5, lane = tid & 31;
    #pragma unroll
    for (int half = 0; half < 2; half++) {
        int tt = w * 2 + half;
        float v[8];
        float m = -1e30f;
        #pragma unroll
        for (int j = 0; j < 8; j++) {
            v[j] = sh[tt * 256 + lane + j * 32];
            m = fmaxf(m, v[j]);
        }
        #pragma unroll
        for (int s = 16; s >= 1; s >>= 1) m = fmaxf(m, __shfl_xor_sync(0xffffffffu, m, s));
        float ssum = 0.f;
        #pragma unroll
        for (int j = 0; j < 8; j++) ssum += expf(v[j] - m);
        #pragma unroll
        for (int s = 16; s >= 1; s >>= 1) ssum += __shfl_xor_sync(0xffffffffu, ssum, s);
        float lse = m + logf(ssum);
        #pragma unroll
        for (int j = 0; j < 8; j++)
            out[(size_t)(t0 + tt) * 256 + lane + j * 32] = v[j] - lse;
    }
}

// ---------------- K5: hL, cL epilogue ----------------
__global__ void tail_kernel(float* __restrict__ out) {
    int i = blockIdx.x * blockDim.x + threadIdx.x;
    if (i < HID) {
        out[(size_t)L_SEQ * 256 + i] = g_hs[(size_t)L_SEQ * HID + i];   // hL
        out[(size_t)L_SEQ * 256 + HID + i] = g_cL[i];                   // cL
    }
}

// ---------------- launch ----------------
extern "C" void kernel_launch(void* const* d_in, const int* in_sizes, int n_in,
                              void* d_out, int out_size) {
    const int*   ids   = (const int*)d_in[0];
    const float* h0    = (const float*)d_in[1];
    const float* c0    = (const float*)d_in[2];
    const float* W_emb = (const float*)d_in[3];
    const float* W_ih  = (const float*)d_in[4];
    const float* W_hh  = (const float*)d_in[5];
    const float* b_ih  = (const float*)d_in[6];
    const float* b_hh  = (const float*)d_in[7];
    const float* W_out = (const float*)d_in[8];
    const float* b_out = (const float*)d_in[9];
    float* out = (float*)d_out;

    cudaFuncSetAttribute(scan_kernel, cudaFuncAttributeMaxDynamicSharedMemorySize, SCAN_SMEM);
    cudaFuncSetAttribute(out_kernel,  cudaFuncAttributeMaxDynamicSharedMemorySize, 16 * HID * 4);

    init_kernel<<<8, 1024>>>(h0);
    conv_kernel<<<4096, 256>>>(W_hh);
    xg_gemm<<<dim3(G4 / 64, NLET / 64), 256>>>(W_emb, W_ih, b_ih, b_hh);
    scan_kernel<<<NB + 1, TPB, SCAN_SMEM>>>(ids, c0);
    out_kernel<<<L_SEQ / 16, 256, 16 * HID * 4>>>(W_out, b_out, out);
    tail_kernel<<<2, 1024>>>(out);
}

// round 14
// speedup vs baseline: 1.2564x; 1.2564x over previous
#include <cuda_runtime.h>
#include <cuda_bf16.h>
#include <cstdint>

// Problem dims
#define L_SEQ   4096
#define HID     2048
#define EMB     1024
#define G4      8192      // 4*HID
#define NLET    256

// Scan kernel config
#define NB      128       // persistent worker blocks; +1 aggregator block
#define TPB     1024
#define HPB     16        // h indices per block

// Dual-row packed weights: u32 = {bf16 W[2k][c] (lo), bf16 W[2k+1][c] (hi)}
#define SDR     24
#define W_S_BYTES   (SDR * HID * 4)              // 196608 (24 dual-rows x 2048 u32)
#define SCAN_SMEM   (W_S_BYTES + 2 * 64 * 4 * 4) // + red[2][64][4] f32

// ---------------- device globals (scratch; no allocation allowed) ----------------
__device__ unsigned g_Whd[(size_t)(G4 / 2) * HID];     // 32 MB dual-row packed bf16 weights
__device__ float g_xg[(size_t)NLET * G4];              // 8 MB gate table
__device__ float g_hs[(size_t)(L_SEQ + 1) * HID];      // 32 MB h history (row 0 = h0)
__device__ float g_cL[HID];
__device__ __align__(128) unsigned g_flagsc[NB];       // compact per-block flags (1 writer; aggregator-only pollers)
__device__ unsigned g_epoch[4 * 8 * 64];               // [quarter][8 replicas], 256B stride, 1 writer each

// ---------------- helpers ----------------
__device__ __forceinline__ unsigned ld_acq(const unsigned* p) {
    unsigned v;
    asm volatile("ld.global.acquire.gpu.u32 %0, [%1];" : "=r"(v) : "l"(p) : "memory");
    return v;
}
__device__ __forceinline__ void st_rel(unsigned* p, unsigned v) {
    asm volatile("st.global.release.gpu.u32 [%0], %1;" :: "l"(p), "r"(v) : "memory");
}

__device__ __forceinline__ float sigmoid_f(float x) {
    return __fdividef(1.f, 1.f + __expf(-x));
}
__device__ __forceinline__ float tanh_f(float x) {
    float xc = fminf(fmaxf(x, -15.f), 15.f);
    float e2 = __expf(2.f * xc);
    return __fdividef(e2 - 1.f, e2 + 1.f);
}

// {h,h} packed f32x2
__device__ __forceinline__ unsigned long long splat2(float h) {
    unsigned long long r;
    asm("mov.b64 %0, {%1, %1};" : "=l"(r) : "f"(h));
    return r;
}
// acc(f32x2) += {bf16lo(u), bf16hi(u)} * hs   (2 fp32 MACs, exact fp32 math)
__device__ __forceinline__ void ffma2c(unsigned long long& acc, unsigned u, unsigned long long hs) {
    asm("{\n\t"
        ".reg .b32 lo, hi;\n\t"
        ".reg .b64 wp;\n\t"
        "shl.b32 lo, %1, 16;\n\t"
        "and.b32 hi, %1, 0xffff0000;\n\t"
        "mov.b64 wp, {lo, hi};\n\t"
        "fma.rn.f32x2 %0, wp, %2, %0;\n\t"
        "}" : "+l"(acc) : "r"(u), "l"(hs));
}
__device__ __forceinline__ void unpack2(unsigned long long a, float& x, float& y) {
    asm("mov.b64 {%0, %1}, %2;" : "=f"(x), "=f"(y) : "l"(a));
}

// ---------------- K0: reset barrier state, init hs[0] = h0 ----------------
__global__ void init_kernel(const float* __restrict__ h0) {
    int i = blockIdx.x * blockDim.x + threadIdx.x;
    if (i < HID) g_hs[i] = h0[i];
    if (i < NB) g_flagsc[i] = 0u;
    if (i < 4 * 8 * 64) g_epoch[i] = 0u;
}

// ---------------- K1: convert W_hh fp32 -> dual-row packed bf16 ----------------
// g_Whd[dr*2048 + c] = {bf16(W[2dr][c]), bf16(W[2dr+1][c])}
__global__ void conv_kernel(const float* __restrict__ W) {
    size_t n = (size_t)(G4 / 2) * HID;
    size_t stride = (size_t)gridDim.x * blockDim.x;
    for (size_t idx = blockIdx.x * (size_t)blockDim.x + threadIdx.x; idx < n; idx += stride) {
        size_t dr = idx >> 11, c = idx & 2047;
        float w0 = W[(2 * dr) * HID + c];
        float w1 = W[(2 * dr + 1) * HID + c];
        __nv_bfloat162 p = __floats2bfloat162_rn(w0, w1);   // .x = lo = even row
        g_Whd[idx] = *reinterpret_cast<unsigned*>(&p);
    }
}

// ---------------- K2: xg_table[256,8192] = W_emb @ W_ih^T + (b_ih+b_hh) ----------------
__global__ void xg_gemm(const float* __restrict__ A /*W_emb [256,1024]*/,
                        const float* __restrict__ B /*W_ih [8192,1024]*/,
                        const float* __restrict__ b_ih,
                        const float* __restrict__ b_hh) {
    __shared__ float As[16][65];
    __shared__ float Bs[16][65];
    int jt = blockIdx.x * 64;   // gate dim
    int lt = blockIdx.y * 64;   // letter dim
    int tid = threadIdx.x;
    int tx = tid & 15, ty = tid >> 4;
    float acc[4][4] = {};
    for (int k0 = 0; k0 < EMB; k0 += 16) {
        #pragma unroll
        for (int i = 0; i < 4; i++) {
            int idx = tid + i * 256;
            int k = idx & 15, l = idx >> 4;
            As[k][l] = A[(size_t)(lt + l) * EMB + k0 + k];
            Bs[k][l] = B[(size_t)(jt + l) * EMB + k0 + k];
        }
        __syncthreads();
        #pragma unroll
        for (int k = 0; k < 16; k++) {
            float a[4], bb[4];
            #pragma unroll
            for (int i = 0; i < 4; i++) a[i] = As[k][ty * 4 + i];
            #pragma unroll
            for (int j = 0; j < 4; j++) bb[j] = Bs[k][tx * 4 + j];
            #pragma unroll
            for (int i = 0; i < 4; i++)
                #pragma unroll
                for (int j = 0; j < 4; j++)
                    acc[i][j] = fmaf(a[i], bb[j], acc[i][j]);
        }
        __syncthreads();
    }
    #pragma unroll
    for (int i = 0; i < 4; i++) {
        int l = lt + ty * 4 + i;
        #pragma unroll
        for (int j = 0; j < 4; j++) {
            int jj = jt + tx * 4 + j;
            g_xg[(size_t)l * G4 + jj] = acc[i][j] + b_ih[jj] + b_hh[jj];
        }
    }
}

// ---------------- K3: persistent LSTM scan ----------------
// Worker block b (0..127) owns h-indices [16b,16b+16) -> 64 gate rows; row-group
// rg 0..7 has rows rr 0..7, paired as dual-rows p = rr/2. p=0..2 in smem,
// p=3 (rows 6,7) loop-invariant in registers.
// WARP MAP (R14): rg = w & 7, cg = w >> 3 — the 8 warps of each h-quarter (cg)
// now spread across all 4 SMSPs, so the post-straggler compute burst issues on
// all schedulers instead of one.
// Dual-row global index: dr = gate*1024 + 8b + ((rg&1)<<2) + p, gate = rg>>1.
// Block 128 = aggregator: warp q polls quarter q's 32 compact flags (one 128B
// line) and releases epoch[q] (8 single-writer replicas).
__global__ void __launch_bounds__(TPB, 1)
scan_kernel(const int* __restrict__ ids, const float* __restrict__ c0) {
    const int tid = threadIdx.x;
    const int b   = blockIdx.x;

    // ---- aggregator block ----
    if (b == NB) {
        const int w = tid >> 5, lane = tid & 31;
        if (w < 4) {  // warp w owns quarter w (blocks w*32 .. w*32+31)
            const unsigned* f = &g_flagsc[w * 32 + lane];
            for (int e = 1; e < L_SEQ; e++) {
                const unsigned tgt = (unsigned)e;
                for (;;) {
                    bool ok = (ld_acq(f) >= tgt);
                    if (__all_sync(0xffffffffu, ok)) break;
                }
                if (lane < 8) st_rel(&g_epoch[w * 512 + lane * 64], tgt);
            }
        }
        return;
    }

    extern __shared__ char smraw[];
    uint4* w_s4 = (uint4*)smraw;                          // 24 dual-rows * 512 uint4
    float* red = (float*)(smraw + W_S_BYTES);             // [2][64][4] partials
    float4* red4 = (float4*)red;

    const int base = b * HPB;

    // Preload the 24 smem-resident dual-rows.
    const uint4* whd4 = (const uint4*)g_Whd;              // 512 uint4 per dual-row
    for (int i = tid; i < SDR * 512; i += TPB) {
        int s = i >> 9, r = i & 511;
        int prg = s / 3, p = s - prg * 3;
        int dr = (prg >> 1) * 1024 + 8 * b + ((prg & 1) << 2) + p;
        w_s4[i] = whd4[(size_t)dr * 512 + r];
    }
    float c_reg = 0.f;
    if (tid < HPB) c_reg = c0[base + tid];
    __syncthreads();

    const int w = tid >> 5, lane = tid & 31;
    const int rg = w & 7;            // row group 0..7  (R14: low bits)
    const int cg = w >> 3;           // column group 0..3 (R14: high bits -> SMSP-spread)
    const int gate = rg >> 1;
    // uint4 units: thread offset within a dual-row = cg*128 + q*32 + lane
    const uint4* ws = w_s4 + (size_t)(rg * 3) * 512 + (cg * 128 + lane);
    // This warp consumes h quarter cg -> poll epoch[cg], replica (b+rg)&7.
    const unsigned* ep = &g_epoch[cg * 512 + ((b + rg) & 7) * 64];
    unsigned* own_flag_w = &g_flagsc[b];

    // Loop-invariant streamed dual-row (rows 6,7 of this row-group): load ONCE.
    uint4 sw[4];
    {
        int dr = gate * 1024 + 8 * b + ((rg & 1) << 2) + 3;
        const uint4* wp_g = whd4 + (size_t)dr * 512 + (cg * 128 + lane);
        #pragma unroll
        for (int q = 0; q < 4; q++) sw[q] = wp_g[q * 32];
    }

    for (int t = 0; t < L_SEQ; t++) {
        // Prefetch xg row + letter id (independent of h — start immediately)
        float xg0, xg1, xg2, xg3;
        if (tid < HPB) {
            int sid = __ldg(&ids[t]);
            const float* xr = g_xg + (size_t)sid * G4 + base + tid;
            xg0 = __ldg(xr);
            xg1 = __ldg(xr + HID);
            xg2 = __ldg(xr + 2 * HID);
            xg3 = __ldg(xr + 3 * HID);
        }

        // Per-quarter epoch wait: single-writer line, warp-coalesced poll.
        if (t > 0) {
            const unsigned tgt = (unsigned)t;
            while (ld_acq(ep) < tgt) {}
        }

        // h slice: 4 fully-coalesced 512B LDG.128 (8 same-cg warps share via L1)
        const float4* hb = (const float4*)(g_hs + (size_t)t * HID) + cg * 128;
        float4 hq[4];
        hq[0] = hb[lane]; hq[1] = hb[32 + lane]; hq[2] = hb[64 + lane]; hq[3] = hb[96 + lane];

        // Packed dual-row dot: acc pair p = {sum row 2p, sum row 2p+1}
        unsigned long long ac0 = 0ull, ac1 = 0ull, ac2 = 0ull, ac3 = 0ull;
        #pragma unroll
        for (int q = 0; q < 4; q++) {
            unsigned long long hs0 = splat2(hq[q].x);
            unsigned long long hs1 = splat2(hq[q].y);
            unsigned long long hs2 = splat2(hq[q].z);
            unsigned long long hs3 = splat2(hq[q].w);
            uint4 w0 = ws[q * 32];
            uint4 w1 = ws[512 + q * 32];
            uint4 w2 = ws[1024 + q * 32];
            uint4 w3 = sw[q];
            ffma2c(ac0, w0.x, hs0); ffma2c(ac0, w0.y, hs1); ffma2c(ac0, w0.z, hs2); ffma2c(ac0, w0.w, hs3);
            ffma2c(ac1, w1.x, hs0); ffma2c(ac1, w1.y, hs1); ffma2c(ac1, w1.z, hs2); ffma2c(ac1, w1.w, hs3);
            ffma2c(ac2, w2.x, hs0); ffma2c(ac2, w2.y, hs1); ffma2c(ac2, w2.z, hs2); ffma2c(ac2, w2.w, hs3);
            ffma2c(ac3, w3.x, hs0); ffma2c(ac3, w3.y, hs1); ffma2c(ac3, w3.z, hs2); ffma2c(ac3, w3.w, hs3);
        }
        float acc[8];
        unpack2(ac0, acc[0], acc[1]);
        unpack2(ac1, acc[2], acc[3]);
        unpack2(ac2, acc[4], acc[5]);
        unpack2(ac3, acc[6], acc[7]);

        // Select-exchange multi-row reduction: 8 row-sums in ~35 instrs.
        float a4[4];
        #pragma unroll
        for (int r = 0; r < 4; r++) {
            float send = (lane & 16) ? acc[r] : acc[r + 4];
            float recv = __shfl_xor_sync(0xffffffffu, send, 16);
            float keep = (lane & 16) ? acc[r + 4] : acc[r];
            a4[r] = keep + recv;
        }
        float a2[2];
        #pragma unroll
        for (int r = 0; r < 2; r++) {
            float send = (lane & 8) ? a4[r] : a4[r + 2];
            float recv = __shfl_xor_sync(0xffffffffu, send, 8);
            float keep = (lane & 8) ? a4[r + 2] : a4[r];
            a2[r] = keep + recv;
        }
        {
            float send = (lane & 4) ? a2[0] : a2[1];
            float recv = __shfl_xor_sync(0xffffffffu, send, 4);
            float keep = (lane & 4) ? a2[1] : a2[0];
            float a1 = keep + recv;
            a1 += __shfl_xor_sync(0xffffffffu, a1, 2);
            a1 += __shfl_xor_sync(0xffffffffu, a1, 1);
            if ((lane & 3) == 0) {
                int row = ((lane >> 2) & 1) | (((lane >> 3) & 1) << 1) | (((lane >> 4) & 1) << 2);
                red[(t & 1) * 256 + (rg * 8 + row) * 4 + cg] = a1;
            }
        }
        __syncthreads();

        // fused combine + LSTM cell update (PyTorch gate order i,f,g,o)
        if (tid < HPB) {
            const float4* rp = red4 + (t & 1) * 64;
            float4 r0 = rp[tid];            // gate i partials
            float4 r1 = rp[16 + tid];       // gate f
            float4 r2 = rp[32 + tid];       // gate g
            float4 r3 = rp[48 + tid];       // gate o
            float gi = r0.x + r0.y + r0.z + r0.w + xg0;
            float gf = r1.x + r1.y + r1.z + r1.w + xg1;
            float gg = r2.x + r2.y + r2.z + r2.w + xg2;
            float go = r3.x + r3.y + r3.z + r3.w + xg3;
            float i_ = sigmoid_f(gi);
            float f_ = sigmoid_f(gf);
            float g_ = tanh_f(gg);
            float o_ = sigmoid_f(go);
            c_reg = f_ * c_reg + i_ * g_;
            float hn = o_ * tanh_f(c_reg);
            g_hs[(size_t)(t + 1) * HID + base + tid] = hn;
            if (t == L_SEQ - 1) g_cL[base + tid] = c_reg;
        }
        __syncwarp();
        if (tid == 0) st_rel(own_flag_w, (unsigned)(t + 1));
    }
}

// ---------------- K4: logits + relu + log_softmax ----------------
__global__ void out_kernel(const float* __restrict__ W_out,
                           const float* __restrict__ b_out,
                           float* __restrict__ out) {
    extern __shared__ float sh[];                    // 16*2048 floats
    int t0 = blockIdx.x * 16;
    int tid = threadIdx.x;

    const float4* src = (const float4*)(g_hs + (size_t)(t0 + 1) * HID);
    float4* dst = (float4*)sh;
    #pragma unroll
    for (int i = 0; i < 32; i++) dst[tid + i * 256] = src[tid + i * 256];
    __syncthreads();

    float acc[16];
    #pragma unroll
    for (int tt = 0; tt < 16; tt++) acc[tt] = 0.f;
    const float4* wrow = (const float4*)(W_out + (size_t)tid * HID);
    for (int e4 = 0; e4 < HID / 4; e4++) {
        float4 wv = wrow[e4];
        #pragma unroll
        for (int tt = 0; tt < 16; tt++) {
            float4 h = ((const float4*)(sh + tt * HID))[e4];
            acc[tt] = fmaf(wv.x, h.x, fmaf(wv.y, h.y, fmaf(wv.z, h.z, fmaf(wv.w, h.w, acc[tt]))));
        }
    }
    float bn = b_out[tid];
    __syncthreads();                                  // reuse sh as logits tile [16][256]
    #pragma unroll
    for (int tt = 0; tt < 16; tt++)
        sh[tt * 256 + tid] = fmaxf(acc[tt] + bn, 0.f);   // relu BEFORE softmax (matches ref)
    __syncthreads();

    int w = tid >> 5, lane = tid & 31;
    #pragma unroll
    for (int half = 0; half < 2; half++) {
        int tt = w * 2 + half;
        float v[8];
        float m = -1e30f;
        #pragma unroll
        for (int j = 0; j < 8; j++) {
            v[j] = sh[tt * 256 + lane + j * 32];
            m = fmaxf(m, v[j]);
        }
        #pragma unroll
        for (int s = 16; s >= 1; s >>= 1) m = fmaxf(m, __shfl_xor_sync(0xffffffffu, m, s));
        float ssum = 0.f;
        #pragma unroll
        for (int j = 0; j < 8; j++) ssum += expf(v[j] - m);
        #pragma unroll
        for (int s = 16; s >= 1; s >>= 1) ssum += __shfl_xor_sync(0xffffffffu, ssum, s);
        float lse = m + logf(ssum);
        #pragma unroll
        for (int j = 0; j < 8; j++)
            out[(size_t)(t0 + tt) * 256 + lane + j * 32] = v[j] - lse;
    }
}

// ---------------- K5: hL, cL epilogue ----------------
__global__ void tail_kernel(float* __restrict__ out) {
    int i = blockIdx.x * blockDim.x + threadIdx.x;
    if (i < HID) {
        out[(size_t)L_SEQ * 256 + i] = g_hs[(size_t)L_SEQ * HID + i];   // hL
        out[(size_t)L_SEQ * 256 + HID + i] = g_cL[i];                   // cL
    }
}

// ---------------- launch ----------------
extern "C" void kernel_launch(void* const* d_in, const int* in_sizes, int n_in,
                              void* d_out, int out_size) {
    const int*   ids   = (const int*)d_in[0];
    const float* h0    = (const float*)d_in[1];
    const float* c0    = (const float*)d_in[2];
    const float* W_emb = (const float*)d_in[3];
    const float* W_ih  = (const float*)d_in[4];
    const float* W_hh  = (const float*)d_in[5];
    const float* b_ih  = (const float*)d_in[6];
    const float* b_hh  = (const float*)d_in[7];
    const float* W_out = (const float*)d_in[8];
    const float* b_out = (const float*)d_in[9];
    float* out = (float*)d_out;

    cudaFuncSetAttribute(scan_kernel, cudaFuncAttributeMaxDynamicSharedMemorySize, SCAN_SMEM);
    cudaFuncSetAttribute(out_kernel,  cudaFuncAttributeMaxDynamicSharedMemorySize, 16 * HID * 4);

    init_kernel<<<8, 1024>>>(h0);
    conv_kernel<<<4096, 256>>>(W_hh);
    xg_gemm<<<dim3(G4 / 64, NLET / 64), 256>>>(W_emb, W_ih, b_ih, b_hh);
    scan_kernel<<<NB + 1, TPB, SCAN_SMEM>>>(ids, c0);
    out_kernel<<<L_SEQ / 16, 256, 16 * HID * 4>>>(W_out, b_out, out);
    tail_kernel<<<2, 1024>>>(out);
}